// round 16
// baseline (speedup 1.0000x reference)
#include <cuda_runtime.h>

#define BATCH 4
#define HEADS 12
#define SEQ   2048
#define DK    64
#define TQ    64
#define TK    64
#define NT    (SEQ / TK)
#define LDKV  64   // K/V smem pitch (chunk-swizzled layout, no padding needed)
#define LDM   68   // mask/attn staging pitch
#define LDC   68   // ctx reduce buffer pitch (float4-aligned rows)
#define FULLMASK 0xffffffffu
#define KV_ELEMS (BATCH * HEADS * SEQ * DK)   // 6,291,456 floats

// tf32-pre-rounded K and V (allocation-free scratch)
__device__ float g_Kt[KV_ELEMS];
__device__ float g_Vt[KV_ELEMS];

__device__ __forceinline__ float to_tf32(float x) {
    asm("cvt.rna.tf32.f32 %0, %0;" : "+f"(x));
    return x;
}
__device__ __forceinline__ unsigned ldcvt(const float* p) {
    return __float_as_uint(to_tf32(*p));
}

// D = A(16x8 tf32, row) * B(8x8 tf32, col) + D, fp32 accum
__device__ __forceinline__ void mma_tf32(float d[4], const unsigned a[4],
                                         unsigned b0, unsigned b1) {
    asm volatile(
        "mma.sync.aligned.m16n8k8.row.col.f32.tf32.tf32.f32 "
        "{%0,%1,%2,%3}, {%4,%5,%6,%7}, {%8,%9}, {%0,%1,%2,%3};"
        : "+f"(d[0]), "+f"(d[1]), "+f"(d[2]), "+f"(d[3])
        : "r"(a[0]), "r"(a[1]), "r"(a[2]), "r"(a[3]), "r"(b0), "r"(b1));
}

__device__ __forceinline__ void cp16(float* dst_smem, const float* src) {
    unsigned d = (unsigned)__cvta_generic_to_shared(dst_smem);
    asm volatile("cp.async.cg.shared.global [%0], [%1], 16;" :: "r"(d), "l"(src));
}

// K chunk swizzle: logical float4-chunk c of row r -> phys float offset.
// c = 4t+J (t = lane tg owning k [16t,16t+16), J = lane's load index).
// p = t | ((r^J)&1)<<2 | (J>>1)<<3  => LDS.128 #J conflict-free across 8-lane groups.
__device__ __forceinline__ int kslot(int r, int c) {
    int t = c >> 2, J = c & 3;
    int p = t | (((r ^ J) & 1) << 2) | ((J >> 1) << 3);
    return 4 * p;
}
// V chunk swizzle: p = c ^ f(r&3), f = [0,4,1,5]
__device__ __forceinline__ int fsw(int x) { return ((x & 1) << 2) | (x >> 1); }
__device__ __forceinline__ int vslot(int r, int c) {
    return 4 * (c ^ fsw(r & 3));
}

// ---- prep: round K,V to tf32 once ----
__global__ void __launch_bounds__(256)
prep_kernel(const float* __restrict__ K, const float* __restrict__ V)
{
    int i = blockIdx.x * 256 + threadIdx.x;
    const int N4 = KV_ELEMS / 4;
    if (i < N4) {
        float4 v = *(const float4*)(K + (size_t)i * 4);
        v.x = to_tf32(v.x); v.y = to_tf32(v.y); v.z = to_tf32(v.z); v.w = to_tf32(v.w);
        *(float4*)(g_Kt + (size_t)i * 4) = v;
    } else {
        int j = i - N4;
        float4 v = *(const float4*)(V + (size_t)j * 4);
        v.x = to_tf32(v.x); v.y = to_tf32(v.y); v.z = to_tf32(v.z); v.w = to_tf32(v.w);
        *(float4*)(g_Vt + (size_t)j * 4) = v;
    }
}

__global__ void __launch_bounds__(256, 2)
attn_kernel(const float* __restrict__ Q, const float* __restrict__ M,
            float* __restrict__ ctx_out, float* __restrict__ attn_out)
{
    extern __shared__ float dynsm[];
    float* K0 = dynsm;                  // [TK*LDKV] swizzled
    float* K1 = K0 + TK * LDKV;
    float* V0 = K1 + TK * LDKV;         // [TK*LDKV] swizzled
    float* V1 = V0 + TK * LDKV;
    float* M0 = V1 + TK * LDKV;         // [TQ*LDM] mask / attn staging
    float* M1 = M0 + TQ * LDM;
    __shared__ float s_sums[2 * TQ];
    __shared__ float s_inv[TQ];

    const int qt = blockIdx.x, h = blockIdx.y, b = blockIdx.z;
    const int tid  = threadIdx.x;
    const int lane = tid & 31;
    const int warp = tid >> 5;
    const int mg = warp >> 1;          // rows mg*16 .. +15
    const int ng = warp & 1;           // score cols ng*32 .. +31 within tile
    const int grp = lane >> 2;         // 0..7
    const int tg  = lane & 3;          // 0..3

    const size_t bh = (size_t)b * HEADS + h;
    const float* Qb = Q + (bh * SEQ + (size_t)qt * TQ) * DK;
    const float* Kb = g_Kt + bh * SEQ * DK;
    const float* Vb = g_Vt + bh * SEQ * DK;
    const float* Mb = M + ((size_t)b * SEQ + (size_t)qt * TQ) * SEQ;
    float* Ab = attn_out + (bh * SEQ + (size_t)qt * TQ) * SEQ;
    float* Cb = ctx_out  + (bh * SEQ + (size_t)qt * TQ) * DK;

    const int row0 = mg * 16 + grp;
    const int row1 = row0 + 8;
    const int col_base = ng * 32 + 2 * tg;

    // cp.async destination offsets (loop-invariant per thread: c and r&3 fixed)
    const int cpc  = tid & 15;              // float4 chunk index
    const int cpr0 = tid >> 4;              // base row (rows step by 16 -> r&3 invariant)
    const int koff_cp = kslot(cpr0, cpc);
    const int voff_cp = vslot(cpr0, cpc);
    const int moff_cp = 4 * cpc;

    // K b-frag LDS.128 offsets within a row (J = 0..3), lane-fixed
    int kf[4];
    {
        int g = grp & 1;
        #pragma unroll
        for (int J = 0; J < 4; ++J)
            kf[J] = 4 * (tg | ((g ^ (J & 1)) << 2) | ((J >> 1) << 3));
    }
    // V b-frag LDS.128 offsets (rows have r&3 == tg for both b0/b1 rows)
    const int vfA = 4 * ((2 * grp)     ^ fsw(tg));
    const int vfB = 4 * ((2 * grp + 1) ^ fsw(tg));

    // ---- prologue: stage Q raw (plain pitch-64 layout), build permuted a-frags ----
    for (int i = tid; i < TQ * 16; i += 256) {
        int r = i >> 4, c = (i & 15) << 2;
        *(float4*)&K0[r * LDKV + c] = *(const float4*)(Qb + (size_t)r * DK + c);
    }
    __syncthreads();

    // k-permutation: step j, k-row tg -> k = 16*tg + j ; k-row tg+4 -> k = 16*tg + 8 + j
    unsigned qa[8][4];
    #pragma unroll
    for (int j = 0; j < 8; ++j) {
        qa[j][0] = ldcvt(&K0[row0 * LDKV + 16 * tg + j]);
        qa[j][1] = ldcvt(&K0[row1 * LDKV + 16 * tg + j]);
        qa[j][2] = ldcvt(&K0[row0 * LDKV + 16 * tg + 8 + j]);
        qa[j][3] = ldcvt(&K0[row1 * LDKV + 16 * tg + 8 + j]);
    }
    __syncthreads();

    const int src0 = (lane & ~3) | (tg >> 1);
    const int src1 = src0 + 2;
    const bool odd = (tg & 1) != 0;

    // ======================= PASS 1: rowsums only =======================
    #pragma unroll
    for (int it = 0; it < 4; ++it) {
        int r = cpr0 + it * 16;
        cp16(K0 + r * LDKV + koff_cp, Kb + (size_t)r * DK + 4 * cpc);
        cp16(M0 + r * LDM + moff_cp, Mb + (size_t)r * SEQ + 4 * cpc);
    }
    asm volatile("cp.async.commit_group;");

    float rsum_lo = 0.f, rsum_hi = 0.f;

    for (int kt = 0; kt < NT; ++kt) {
        float* Ks = (kt & 1) ? K1 : K0;
        float* Ms = (kt & 1) ? M1 : M0;

        if (kt + 1 < NT) {
            float* Kn = (kt & 1) ? K0 : K1;
            float* Mn = (kt & 1) ? M0 : M1;
            const float* kg = Kb + (size_t)(kt + 1) * TK * DK;
            const float* mgp = Mb + (kt + 1) * TK;
            #pragma unroll
            for (int it = 0; it < 4; ++it) {
                int r = cpr0 + it * 16;
                cp16(Kn + r * LDKV + koff_cp, kg + (size_t)r * DK + 4 * cpc);
                cp16(Mn + r * LDM + moff_cp, mgp + (size_t)r * SEQ + 4 * cpc);
            }
            asm volatile("cp.async.commit_group;");
            asm volatile("cp.async.wait_group 1;");
        } else {
            asm volatile("cp.async.wait_group 0;");
        }
        __syncthreads();

        float sd[4][4];
        #pragma unroll
        for (int nt = 0; nt < 4; ++nt)
            #pragma unroll
            for (int j = 0; j < 4; ++j) sd[nt][j] = 0.f;

        #pragma unroll
        for (int np = 0; np < 2; ++np) {
            const float* baseA = &Ks[(ng * 32 + (2 * np)     * 8 + grp) * LDKV];
            const float* baseB = &Ks[(ng * 32 + (2 * np + 1) * 8 + grp) * LDKV];
            float ka[16], kb[16];
            #pragma unroll
            for (int J = 0; J < 4; ++J) {
                *(float4*)&ka[4 * J] = *(const float4*)(baseA + kf[J]);
                *(float4*)&kb[4 * J] = *(const float4*)(baseB + kf[J]);
            }
            #pragma unroll
            for (int j = 0; j < 8; ++j) {
                mma_tf32(sd[2 * np],     qa[j], __float_as_uint(ka[j]), __float_as_uint(ka[8 + j]));
                mma_tf32(sd[2 * np + 1], qa[j], __float_as_uint(kb[j]), __float_as_uint(kb[8 + j]));
            }
        }

        #pragma unroll
        for (int nt = 0; nt < 4; ++nt) {
            int cs = col_base + nt * 8;
            float2 m0 = *(const float2*)&Ms[row0 * LDM + cs];
            float2 m1 = *(const float2*)&Ms[row1 * LDM + cs];
            rsum_lo += __expf(sd[nt][0] * 0.125f) * m0.x
                     + __expf(sd[nt][1] * 0.125f) * m0.y;
            rsum_hi += __expf(sd[nt][2] * 0.125f) * m1.x
                     + __expf(sd[nt][3] * 0.125f) * m1.y;
        }
        __syncthreads();
    }

    // ---- rowsums -> inverse denominators ----
    rsum_lo += __shfl_xor_sync(FULLMASK, rsum_lo, 1);
    rsum_lo += __shfl_xor_sync(FULLMASK, rsum_lo, 2);
    rsum_hi += __shfl_xor_sync(FULLMASK, rsum_hi, 1);
    rsum_hi += __shfl_xor_sync(FULLMASK, rsum_hi, 2);
    if (tg == 0) {
        s_sums[ng * TQ + row0] = rsum_lo;
        s_sums[ng * TQ + row1] = rsum_hi;
    }
    __syncthreads();
    if (tid < TQ) s_inv[tid] = 1.f / (s_sums[tid] + s_sums[TQ + tid] + 1e-8f);
    __syncthreads();

    const float ilo = s_inv[row0];
    const float ihi = s_inv[row1];

    // ================= PASS 2: normalized attn + context =================
    #pragma unroll
    for (int it = 0; it < 4; ++it) {
        int r = cpr0 + it * 16;
        cp16(K0 + r * LDKV + koff_cp, Kb + (size_t)r * DK + 4 * cpc);
        cp16(V0 + r * LDKV + voff_cp, Vb + (size_t)r * DK + 4 * cpc);
        cp16(M0 + r * LDM + moff_cp, Mb + (size_t)r * SEQ + 4 * cpc);
    }
    asm volatile("cp.async.commit_group;");

    float ctxa[8][4];
    #pragma unroll
    for (int i = 0; i < 8; ++i)
        #pragma unroll
        for (int j = 0; j < 4; ++j) ctxa[i][j] = 0.f;

    for (int kt = 0; kt < NT; ++kt) {
        float* Ks = (kt & 1) ? K1 : K0;
        float* Vs = (kt & 1) ? V1 : V0;
        float* Ms = (kt & 1) ? M1 : M0;

        if (kt + 1 < NT) {
            float* Kn = (kt & 1) ? K0 : K1;
            float* Vn = (kt & 1) ? V0 : V1;
            float* Mn = (kt & 1) ? M0 : M1;
            const float* kg = Kb + (size_t)(kt + 1) * TK * DK;
            const float* vg = Vb + (size_t)(kt + 1) * TK * DK;
            const float* mgp = Mb + (kt + 1) * TK;
            #pragma unroll
            for (int it = 0; it < 4; ++it) {
                int r = cpr0 + it * 16;
                cp16(Kn + r * LDKV + koff_cp, kg + (size_t)r * DK + 4 * cpc);
                cp16(Vn + r * LDKV + voff_cp, vg + (size_t)r * DK + 4 * cpc);
                cp16(Mn + r * LDM + moff_cp, mgp + (size_t)r * SEQ + 4 * cpc);
            }
            asm volatile("cp.async.commit_group;");
            asm volatile("cp.async.wait_group 1;");
        } else {
            asm volatile("cp.async.wait_group 0;");
        }
        __syncthreads();

        // ---- scores (recompute; same permuted-k order as pass 1) ----
        float sd[4][4];
        #pragma unroll
        for (int nt = 0; nt < 4; ++nt)
            #pragma unroll
            for (int j = 0; j < 4; ++j) sd[nt][j] = 0.f;

        #pragma unroll
        for (int np = 0; np < 2; ++np) {
            const float* baseA = &Ks[(ng * 32 + (2 * np)     * 8 + grp) * LDKV];
            const float* baseB = &Ks[(ng * 32 + (2 * np + 1) * 8 + grp) * LDKV];
            float ka[16], kb[16];
            #pragma unroll
            for (int J = 0; J < 4; ++J) {
                *(float4*)&ka[4 * J] = *(const float4*)(baseA + kf[J]);
                *(float4*)&kb[4 * J] = *(const float4*)(baseB + kf[J]);
            }
            #pragma unroll
            for (int j = 0; j < 8; ++j) {
                mma_tf32(sd[2 * np],     qa[j], __float_as_uint(ka[j]), __float_as_uint(ka[8 + j]));
                mma_tf32(sd[2 * np + 1], qa[j], __float_as_uint(kb[j]), __float_as_uint(kb[8 + j]));
            }
        }

        // ---- e_norm = exp(s/8)*mask*inv ; stage into Ms ----
        #pragma unroll
        for (int nt = 0; nt < 4; ++nt) {
            int cs = col_base + nt * 8;
            float2 m0 = *(const float2*)&Ms[row0 * LDM + cs];
            float2 m1 = *(const float2*)&Ms[row1 * LDM + cs];
            float e0 = __expf(sd[nt][0] * 0.125f) * m0.x * ilo;
            float e1 = __expf(sd[nt][1] * 0.125f) * m0.y * ilo;
            float e2 = __expf(sd[nt][2] * 0.125f) * m1.x * ihi;
            float e3 = __expf(sd[nt][3] * 0.125f) * m1.y * ihi;
            *(float2*)&Ms[row0 * LDM + cs] = make_float2(e0, e1);
            *(float2*)&Ms[row1 * LDM + cs] = make_float2(e2, e3);
            sd[nt][0] = e0; sd[nt][1] = e1; sd[nt][2] = e2; sd[nt][3] = e3;
        }

        // ---- D-layout -> A-layout via shuffles ----
        unsigned ea[4][4];
        #pragma unroll
        for (int nt = 0; nt < 4; ++nt) {
            float x0 = __shfl_sync(FULLMASK, sd[nt][0], src0);
            float x1 = __shfl_sync(FULLMASK, sd[nt][1], src0);
            float x2 = __shfl_sync(FULLMASK, sd[nt][2], src0);
            float x3 = __shfl_sync(FULLMASK, sd[nt][3], src0);
            float y0 = __shfl_sync(FULLMASK, sd[nt][0], src1);
            float y1 = __shfl_sync(FULLMASK, sd[nt][1], src1);
            float y2 = __shfl_sync(FULLMASK, sd[nt][2], src1);
            float y3 = __shfl_sync(FULLMASK, sd[nt][3], src1);
            ea[nt][0] = __float_as_uint(to_tf32(odd ? x1 : x0));
            ea[nt][1] = __float_as_uint(to_tf32(odd ? x3 : x2));
            ea[nt][2] = __float_as_uint(to_tf32(odd ? y1 : y0));
            ea[nt][3] = __float_as_uint(to_tf32(odd ? y3 : y2));
        }

        // ---- ctx += E_norm . V  (fragment ct covers dk cols {8q+ct}) ----
        #pragma unroll
        for (int nt = 0; nt < 4; ++nt) {
            int rb = ng * 32 + nt * 8;
            const float* v0b = &Vs[(rb + tg)     * LDKV];
            const float* v1b = &Vs[(rb + tg + 4) * LDKV];
            float vr0[8], vr1[8];
            *(float4*)&vr0[0] = *(const float4*)(v0b + vfA);
            *(float4*)&vr0[4] = *(const float4*)(v0b + vfB);
            *(float4*)&vr1[0] = *(const float4*)(v1b + vfA);
            *(float4*)&vr1[4] = *(const float4*)(v1b + vfB);
            #pragma unroll
            for (int ct = 0; ct < 8; ++ct)
                mma_tf32(ctxa[ct], ea[nt],
                         __float_as_uint(vr0[ct]), __float_as_uint(vr1[ct]));
        }
        __syncthreads();   // staged e visible; tile reads done

        // ---- coalesced streaming write of normalized attn tile ----
        {
            float* ag = Ab + kt * TK;
            #pragma unroll
            for (int it = 0; it < 4; ++it) {
                int idx = tid + it * 256;
                int r = idx >> 4, c4 = (idx & 15) << 2;
                float4 v = *(float4*)&Ms[r * LDM + c4];
                __stcs((float4*)(ag + (size_t)r * SEQ + c4), v);
            }
        }
        __syncthreads();   // staging reads done before next cp.async overwrites
    }

    // ---- ctx reduction: n-col of ctxa[ct] regs: c0->16tg+ct, c1->16tg+8+ct ----
    float* ctxbuf = dynsm;   // tile buffers dead
    if (ng == 0) {
        #pragma unroll
        for (int ct = 0; ct < 8; ++ct) {
            ctxbuf[row0 * LDC + 16 * tg + ct]     = ctxa[ct][0];
            ctxbuf[row0 * LDC + 16 * tg + 8 + ct] = ctxa[ct][1];
            ctxbuf[row1 * LDC + 16 * tg + ct]     = ctxa[ct][2];
            ctxbuf[row1 * LDC + 16 * tg + 8 + ct] = ctxa[ct][3];
        }
    }
    __syncthreads();
    if (ng == 1) {
        #pragma unroll
        for (int ct = 0; ct < 8; ++ct) {
            ctxbuf[row0 * LDC + 16 * tg + ct]     += ctxa[ct][0];
            ctxbuf[row0 * LDC + 16 * tg + 8 + ct] += ctxa[ct][1];
            ctxbuf[row1 * LDC + 16 * tg + ct]     += ctxa[ct][2];
            ctxbuf[row1 * LDC + 16 * tg + 8 + ct] += ctxa[ct][3];
        }
    }
    __syncthreads();
    for (int idx = tid; idx < TQ * 16; idx += 256) {
        int r = idx >> 4, c4 = (idx & 15) << 2;
        *(float4*)(Cb + (size_t)r * DK + c4) = *(float4*)&ctxbuf[r * LDC + c4];
    }
}

extern "C" void kernel_launch(void* const* d_in, const int* in_sizes, int n_in,
                              void* d_out, int out_size)
{
    const float* Q = (const float*)d_in[0];
    const float* K = (const float*)d_in[1];
    const float* V = (const float*)d_in[2];
    const float* M = (const float*)d_in[3];

    float* ctx  = (float*)d_out;                                    // B*H*S*DK
    float* attn = (float*)d_out + (size_t)BATCH * HEADS * SEQ * DK; // B*H*S*S

    prep_kernel<<<(2 * (KV_ELEMS / 4) + 255) / 256, 256>>>(K, V);

    const size_t smem = (size_t)(4 * TK * LDKV + 2 * TQ * LDM) * sizeof(float); // 100352 B
    cudaFuncSetAttribute(attn_kernel, cudaFuncAttributeMaxDynamicSharedMemorySize, (int)smem);

    dim3 grid(SEQ / TQ, HEADS, BATCH);
    attn_kernel<<<grid, 256, smem>>>(Q, M, ctx, attn);
}